// round 1
// baseline (speedup 1.0000x reference)
#include <cuda_runtime.h>
#include <cuda_bf16.h>

// AdjacencyMatrixLayer: out[b,i,j] = softmax_j( exp( -||x_bi - x_bj||^2 * p ) )
// B=128, K=1024. Output 128*1024*1024 fp32.
//
// Strategy:
//  - One block per (b, 16-row tile): grid = 128 * 64 = 8192 blocks, 256 threads.
//  - Stage all 1024 points of batch b in smem as float4 (x,y,z,norm) = 16 KB.
//  - Each of the 8 warps owns 2 rows. Per k-step, one LDS.128 of point j is
//    shared between both rows (halves smem crossbar traffic).
//  - 32 values/row/lane held in REGISTERS across the sum -> normalize pass,
//    so exp() is evaluated exactly once per output (MUFU floor ~61us).
//  - Warp-shuffle reduction for the row sum; fast reciprocal; coalesced
//    128B STG per k-step.

static constexpr int K = 1024;
static constexpr int ROWS_PER_BLOCK = 16;
static constexpr int THREADS = 256;

__global__ void __launch_bounds__(THREADS, 1)
adjacency_softmax_kernel(const float* __restrict__ coords,
                         const float* __restrict__ prec,
                         float* __restrict__ out)
{
    __shared__ float4 pk[K];  // 16 KB: (x, y, z, ||x||^2) per point

    const int b        = blockIdx.x >> 6;          // / (K / ROWS_PER_BLOCK)
    const int row_base = (blockIdx.x & 63) << 4;   // * ROWS_PER_BLOCK
    const float p = prec[0];

    const float* cb = coords + (size_t)b * K * 3;
    const int tid = threadIdx.x;

    // Cooperative load of all K points; compute squared norm on the way in.
    #pragma unroll
    for (int j = tid; j < K; j += THREADS) {
        float x = cb[j * 3 + 0];
        float y = cb[j * 3 + 1];
        float z = cb[j * 3 + 2];
        pk[j] = make_float4(x, y, z, x * x + y * y + z * z);
    }
    __syncthreads();

    const int wid  = tid >> 5;
    const int lane = tid & 31;

    // Each warp handles two rows i0, i1 (shares the j-point loads).
    const int i0 = row_base + wid * 2;
    const int i1 = i0 + 1;

    const float4 a0 = pk[i0];   // smem broadcast (conflict-free)
    const float4 a1 = pk[i1];

    float v0[32], v1[32];
    float s0 = 0.0f, s1 = 0.0f;

    #pragma unroll
    for (int k = 0; k < 32; k++) {
        const float4 c = pk[k * 32 + lane];   // LDS.128, conflict-free
        // d = ||a||^2 + ||c||^2 - 2 a.c   (matches reference exactly)
        float d0 = a0.w + c.w - 2.0f * (a0.x * c.x + a0.y * c.y + a0.z * c.z);
        float d1 = a1.w + c.w - 2.0f * (a1.x * c.x + a1.y * c.y + a1.z * c.z);
        // A = exp(-d*p); softmax numerator = exp(A). A in (0,1], no max-sub needed.
        float e0 = __expf(__expf(-d0 * p));
        float e1 = __expf(__expf(-d1 * p));
        v0[k] = e0;  s0 += e0;
        v1[k] = e1;  s1 += e1;
    }

    // Warp-level row-sum reduction.
    #pragma unroll
    for (int o = 16; o > 0; o >>= 1) {
        s0 += __shfl_xor_sync(0xFFFFFFFFu, s0, o);
        s1 += __shfl_xor_sync(0xFFFFFFFFu, s1, o);
    }

    const float inv0 = __fdividef(1.0f, s0);
    const float inv1 = __fdividef(1.0f, s1);

    float* __restrict__ o0 = out + ((size_t)b * K + i0) * K;
    float* __restrict__ o1 = o0 + K;

    #pragma unroll
    for (int k = 0; k < 32; k++) {
        o0[k * 32 + lane] = v0[k] * inv0;   // coalesced 128B per warp-instr
        o1[k * 32 + lane] = v1[k] * inv1;
    }
}

extern "C" void kernel_launch(void* const* d_in, const int* in_sizes, int n_in,
                              void* d_out, int out_size)
{
    const float* coords = (const float*)d_in[0];   // [128, 1024, 3] f32
    const float* prec   = (const float*)d_in[1];   // [1] f32
    float* out          = (float*)d_out;           // [128, 1024, 1024] f32

    const int B = 128;
    dim3 grid(B * (K / ROWS_PER_BLOCK));   // 8192
    adjacency_softmax_kernel<<<grid, THREADS>>>(coords, prec, out);
}